// round 8
// baseline (speedup 1.0000x reference)
#include <cuda_runtime.h>
#include <cuda_bf16.h>

#define D 128
#define HEADS 8
#define UNITS 16
#define MAX_NODES 50000
#define MAX_EDGES 800000
#define SCAN_BLK 1024
#define MAX_SCAN_BLOCKS ((MAX_NODES + SCAN_BLK - 1) / SCAN_BLK)
#define HIST_BLOCKS 512

typedef unsigned long long ull;

// Scratch (device globals: no allocation allowed; zero-initialized at load)
__device__ float g_xp[MAX_NODES * D];        // projected features, 25.6 MB
__device__ int   g_deg[MAX_NODES];           // in-degree histogram (kept zeroed)
__device__ int   g_rowptr[MAX_NODES + 1];    // CSR row pointers (by target)
__device__ int   g_cursor[MAX_NODES];        // scatter cursors
__device__ int   g_csrc[MAX_EDGES];          // CSR: source node per slot
__device__ int   g_aggval[MAX_SCAN_BLOCKS];  // lookback: block aggregates
__device__ int   g_prefval[MAX_SCAN_BLOCKS]; // lookback: inclusive prefixes
__device__ int   g_state[MAX_SCAN_BLOCKS];   // lookback: 0/1/2 (kept zeroed)

// ---------------------------------------------------------------------------
// 1. fused: projection GEMM (blocks [0, NB_GEMM)) + target histogram (rest).
//    Independent outputs, disjoint pipes (FMA/LDS vs L2-atomic) -> overlap.
// ---------------------------------------------------------------------------
__global__ void gemm_hist_kernel(const float* __restrict__ x,
                                 const float* __restrict__ W,
                                 const int2* __restrict__ edges,
                                 int n_nodes, int n_edges, int nb_gemm) {
    if ((int)blockIdx.x >= nb_gemm) {
        // ---- histogram part: grid-stride over edges ----
        int b = blockIdx.x - nb_gemm;
        int stride = HIST_BLOCKS * 128;
        for (int e = b * 128 + threadIdx.x; e < n_edges; e += stride)
            atomicAdd(&g_deg[edges[e].y], 1);
        return;
    }

    // ---- GEMM part: g_xp[n][j] = sum_k x[n][k]*W[k][j], packed fma.rn.f32x2
    __shared__ ulonglong2 xs[32 * 32];  // 32 nodes x 128 floats, as 2x f32x2
    const int t = threadIdx.x;          // 0..127 output column
    const int n0 = blockIdx.x * 32;
    const int nrows = min(32, n_nodes - n0);

    const float4* x4 = reinterpret_cast<const float4*>(x);
#pragma unroll
    for (int q = 0; q < 8; q++) {
        int idx = q * 128 + t;
        int i = idx >> 5;
        int kq = idx & 31;
        float4 v = (i < nrows) ? x4[(size_t)(n0 + i) * 32 + kq]
                               : make_float4(0.f, 0.f, 0.f, 0.f);
        xs[idx] = *reinterpret_cast<ulonglong2*>(&v);
    }
    __syncthreads();

    ull acc2[32];
#pragma unroll
    for (int i = 0; i < 32; i++) acc2[i] = 0ull;  // {+0.f, +0.f}

    for (int kq = 0; kq < 32; kq++) {
        const float w0 = W[(4 * kq + 0) * D + t];
        const float w1 = W[(4 * kq + 1) * D + t];
        const float w2 = W[(4 * kq + 2) * D + t];
        const float w3 = W[(4 * kq + 3) * D + t];
        ull wp0, wp1;
        asm("mov.b64 %0, {%1,%2};" : "=l"(wp0) : "f"(w0), "f"(w1));
        asm("mov.b64 %0, {%1,%2};" : "=l"(wp1) : "f"(w2), "f"(w3));
#pragma unroll
        for (int i = 0; i < 32; i++) {
            ulonglong2 xv = xs[i * 32 + kq];  // broadcast across block
            asm("fma.rn.f32x2 %0, %1, %2, %0;" : "+l"(acc2[i]) : "l"(xv.x), "l"(wp0));
            asm("fma.rn.f32x2 %0, %1, %2, %0;" : "+l"(acc2[i]) : "l"(xv.y), "l"(wp1));
        }
    }

    for (int i = 0; i < nrows; i++) {
        float lo, hi;
        asm("mov.b64 {%0,%1}, %2;" : "=f"(lo), "=f"(hi) : "l"(acc2[i]));
        g_xp[(size_t)(n0 + i) * D + t] = lo + hi;
    }
}

// ---------------------------------------------------------------------------
// 2. single-pass exclusive scan (decoupled lookback). 49 blocks, all resident
//    in wave 1 -> lookback cannot deadlock. Also restores g_deg to zero for
//    the next graph replay (globals start zeroed at module load).
// ---------------------------------------------------------------------------
__global__ void scan_onepass_kernel(int n_nodes, int n_edges) {
    __shared__ int wsum[32];
    __shared__ int s_excl;
    const int tid = threadIdx.x;
    const int lane = tid & 31;
    const int warp = tid >> 5;
    const int bid = blockIdx.x;
    const int i = bid * SCAN_BLK + tid;

    int v = (i < n_nodes) ? g_deg[i] : 0;
    if (i < n_nodes) g_deg[i] = 0;   // restore for next replay

    int incl = v;
#pragma unroll
    for (int off = 1; off < 32; off <<= 1) {
        int t = __shfl_up_sync(0xFFFFFFFFu, incl, off);
        if (lane >= off) incl += t;
    }
    if (lane == 31) wsum[warp] = incl;
    __syncthreads();
    if (warp == 0) {
        int wv = wsum[lane];
        int winc = wv;
#pragma unroll
        for (int off = 1; off < 32; off <<= 1) {
            int t = __shfl_up_sync(0xFFFFFFFFu, winc, off);
            if (lane >= off) winc += t;
        }
        wsum[lane] = winc - wv;  // exclusive warp offsets
        int tot = __shfl_sync(0xFFFFFFFFu, winc, 31);
        if (lane == 0) {
            // publish aggregate
            g_aggval[bid] = tot;
            __threadfence();
            atomicExch(&g_state[bid], 1);
            // lookback
            int excl = 0;
            for (int p = bid - 1; p >= 0;) {
                int st;
                do { st = atomicAdd(&g_state[p], 0); } while (st == 0);
                if (st == 2) { excl += atomicAdd(&g_prefval[p], 0); break; }
                excl += atomicAdd(&g_aggval[p], 0);
                p--;
            }
            // publish inclusive prefix
            g_prefval[bid] = excl + tot;
            __threadfence();
            atomicExch(&g_state[bid], 2);
            s_excl = excl;
        }
    }
    __syncthreads();

    if (i < n_nodes) {
        int r = incl - v + wsum[warp] + s_excl;
        g_rowptr[i] = r;
        g_cursor[i] = r;
    }
    if (i == 0) g_rowptr[n_nodes] = n_edges;
}

// ---------------------------------------------------------------------------
// 3. scatter sources into CSR slots (int2 edge load); also re-zero the
//    lookback state words for the next graph replay.
// ---------------------------------------------------------------------------
__global__ void scatter_kernel(const int2* __restrict__ edges, int n_edges) {
    int e = blockIdx.x * blockDim.x + threadIdx.x;
    if (e < MAX_SCAN_BLOCKS) g_state[e] = 0;
    if (e >= n_edges) return;
    int2 ed = edges[e];
    int pos = atomicAdd(&g_cursor[ed.y], 1);
    g_csrc[pos] = ed.x;
}

// ---------------------------------------------------------------------------
// 4. fused attention: one warp per target node, software-pipelined (MLP=8).
//    out[tgt] = gelu( (sum_e p_e * xp[src_e]) / (sum_e p_e + 1e-7) + bias )
// ---------------------------------------------------------------------------
__device__ __forceinline__ float gelu_tanh(float v) {
    float c = 0.7978845608028654f * (v + 0.044715f * v * v * v);
    return 0.5f * v * (1.f + tanhf(c));
}

__global__ void attn_kernel(const float* __restrict__ ka1,
                            const float* __restrict__ battn,
                            const float* __restrict__ bias,
                            float* __restrict__ out,
                            int n_nodes) {
    int w = (blockIdx.x * blockDim.x + threadIdx.x) >> 5;
    if (w >= n_nodes) return;
    const int lane = threadIdx.x & 31;
    const int j = lane * 4;

    const int row = __ldg(&g_rowptr[w]);
    const int end = __ldg(&g_rowptr[w + 1]);

    const float4 xt = *reinterpret_cast<const float4*>(&g_xp[(size_t)w * D + j]);
    const float4 kb = *reinterpret_cast<const float4*>(&battn[j]);
    const float4 ka = *reinterpret_cast<const float4*>(&ka1[j]);

    const float tb0 = xt.x + 2.f * kb.x;
    const float tb1 = xt.y + 2.f * kb.y;
    const float tb2 = xt.z + 2.f * kb.z;
    const float tb3 = xt.w + 2.f * kb.w;

    float a0 = 0.f, a1 = 0.f, a2 = 0.f, a3 = 0.f, ssum = 0.f;

    auto process = [&](float4 xv) {
        float s0 = xv.x + tb0; s0 = (s0 > 0.f) ? s0 : 0.2f * s0;
        float s1 = xv.y + tb1; s1 = (s1 > 0.f) ? s1 : 0.2f * s1;
        float s2 = xv.z + tb2; s2 = (s2 > 0.f) ? s2 : 0.2f * s2;
        float s3 = xv.w + tb3; s3 = (s3 > 0.f) ? s3 : 0.2f * s3;
        float part = fmaf(s0, ka.x, fmaf(s1, ka.y, fmaf(s2, ka.z, s3 * ka.w)));
        part += __shfl_xor_sync(0xFFFFFFFFu, part, 1);
        part += __shfl_xor_sync(0xFFFFFFFFu, part, 2);
        float p = __expf(part);
        ssum += p;
        a0 = fmaf(p, xv.x, a0);
        a1 = fmaf(p, xv.y, a1);
        a2 = fmaf(p, xv.z, a2);
        a3 = fmaf(p, xv.w, a3);
    };

    // MLP=8 batched gathers; tail chunk clamps indices and predicates compute
    for (int base = row; base < end; base += 8) {
        const int cnt = end - base;         // >= 1
        const int cmax = cnt - 1;
        int idx[8];
#pragma unroll
        for (int k = 0; k < 8; k++)
            idx[k] = __ldg(&g_csrc[base + min(k, cmax)]);
        float4 vv[8];
#pragma unroll
        for (int k = 0; k < 8; k++)
            vv[k] = *reinterpret_cast<const float4*>(&g_xp[(size_t)idx[k] * D + j]);
#pragma unroll
        for (int k = 0; k < 8; k++)
            if (k < cnt) process(vv[k]);
    }

    const float inv = 1.f / (ssum + 1e-7f);
    const float4 b = *reinterpret_cast<const float4*>(&bias[j]);
    float4 o;
    o.x = gelu_tanh(fmaf(a0, inv, b.x));
    o.y = gelu_tanh(fmaf(a1, inv, b.y));
    o.z = gelu_tanh(fmaf(a2, inv, b.z));
    o.w = gelu_tanh(fmaf(a3, inv, b.w));
    *reinterpret_cast<float4*>(&out[(size_t)w * D + j]) = o;
}

// ---------------------------------------------------------------------------
extern "C" void kernel_launch(void* const* d_in, const int* in_sizes, int n_in,
                              void* d_out, int out_size) {
    const float* x     = (const float*)d_in[0];
    const int*   edges = (const int*)d_in[1];
    const float* W     = (const float*)d_in[2]; // (D, H, U) row-major == D x 128
    const float* ka1   = (const float*)d_in[3];
    const float* battn = (const float*)d_in[4];
    const float* bias  = (const float*)d_in[5];
    float* out = (float*)d_out;

    const int n_nodes = in_sizes[0] / D;
    const int n_edges = in_sizes[1] / 2;
    const int nb = (n_nodes + SCAN_BLK - 1) / SCAN_BLK;
    const int nb_gemm = (n_nodes + 31) / 32;

    // 1. fused projection GEMM + in-degree histogram
    gemm_hist_kernel<<<nb_gemm + HIST_BLOCKS, 128>>>(
        x, W, (const int2*)edges, n_nodes, n_edges, nb_gemm);
    // 2. single-pass exclusive scan -> rowptr/cursor (restores g_deg = 0)
    scan_onepass_kernel<<<nb, SCAN_BLK>>>(n_nodes, n_edges);
    // 3. scatter sources into CSR (restores g_state = 0)
    scatter_kernel<<<(n_edges + 255) / 256, 256>>>((const int2*)edges, n_edges);
    // 4. fused per-node attention (score + softmax + aggregate + bias + gelu)
    {
        int threads = 256;
        int blocks = (n_nodes * 32 + threads - 1) / threads;
        attn_kernel<<<blocks, threads>>>(ka1, battn, bias, out, n_nodes);
    }
}

// round 9
// speedup vs baseline: 1.1202x; 1.1202x over previous
#include <cuda_runtime.h>
#include <cuda_bf16.h>

#define D 128
#define HEADS 8
#define UNITS 16
#define MAX_NODES 50000
#define MAX_EDGES 800000
#define SCAN_BLK 1024
#define MAX_SCAN_BLOCKS ((MAX_NODES + SCAN_BLK - 1) / SCAN_BLK)

typedef unsigned long long ull;

// Scratch (device globals: no allocation allowed; zero-initialized at load)
__device__ float g_xp[MAX_NODES * D];        // projected features, 25.6 MB
__device__ int   g_deg[MAX_NODES];           // in-degree histogram (kept zeroed)
__device__ int   g_rowptr[MAX_NODES + 1];    // CSR row pointers (by target)
__device__ int   g_cursor[MAX_NODES];        // scatter cursors
__device__ int   g_csrc[MAX_EDGES];          // CSR: source node per slot
__device__ int   g_aggval[MAX_SCAN_BLOCKS];  // lookback: block aggregates
__device__ int   g_prefval[MAX_SCAN_BLOCKS]; // lookback: inclusive prefixes
__device__ int   g_state[MAX_SCAN_BLOCKS];   // lookback: 0/1/2 (kept zeroed)

// ---------------------------------------------------------------------------
// GEMM (side stream): g_xp[n][j] = sum_k x[n][k]*W[k][j], packed fma.rn.f32x2
// ---------------------------------------------------------------------------
__global__ void gemm_kernel(const float* __restrict__ x,
                            const float* __restrict__ W,
                            int n_nodes) {
    __shared__ ulonglong2 xs[32 * 32];  // 32 nodes x 128 floats, as 2x f32x2
    const int t = threadIdx.x;          // 0..127 output column
    const int n0 = blockIdx.x * 32;
    const int nrows = min(32, n_nodes - n0);

    const float4* x4 = reinterpret_cast<const float4*>(x);
#pragma unroll
    for (int q = 0; q < 8; q++) {
        int idx = q * 128 + t;
        int i = idx >> 5;
        int kq = idx & 31;
        float4 v = (i < nrows) ? x4[(size_t)(n0 + i) * 32 + kq]
                               : make_float4(0.f, 0.f, 0.f, 0.f);
        xs[idx] = *reinterpret_cast<ulonglong2*>(&v);
    }
    __syncthreads();

    ull acc2[32];
#pragma unroll
    for (int i = 0; i < 32; i++) acc2[i] = 0ull;  // {+0.f, +0.f}

    for (int kq = 0; kq < 32; kq++) {
        const float w0 = W[(4 * kq + 0) * D + t];
        const float w1 = W[(4 * kq + 1) * D + t];
        const float w2 = W[(4 * kq + 2) * D + t];
        const float w3 = W[(4 * kq + 3) * D + t];
        ull wp0, wp1;
        asm("mov.b64 %0, {%1,%2};" : "=l"(wp0) : "f"(w0), "f"(w1));
        asm("mov.b64 %0, {%1,%2};" : "=l"(wp1) : "f"(w2), "f"(w3));
#pragma unroll
        for (int i = 0; i < 32; i++) {
            ulonglong2 xv = xs[i * 32 + kq];  // broadcast across block
            asm("fma.rn.f32x2 %0, %1, %2, %0;" : "+l"(acc2[i]) : "l"(xv.x), "l"(wp0));
            asm("fma.rn.f32x2 %0, %1, %2, %0;" : "+l"(acc2[i]) : "l"(xv.y), "l"(wp1));
        }
    }

    for (int i = 0; i < nrows; i++) {
        float lo, hi;
        asm("mov.b64 {%0,%1}, %2;" : "=f"(lo), "=f"(hi) : "l"(acc2[i]));
        g_xp[(size_t)(n0 + i) * D + t] = lo + hi;
    }
}

// ---------------------------------------------------------------------------
// histogram of targets (int2 edge load)
// ---------------------------------------------------------------------------
__global__ void hist_kernel(const int2* __restrict__ edges, int n_edges) {
    int e = blockIdx.x * blockDim.x + threadIdx.x;
    if (e >= n_edges) return;
    atomicAdd(&g_deg[edges[e].y], 1);
}

// ---------------------------------------------------------------------------
// single-pass exclusive scan (decoupled lookback); restores g_deg = 0.
// 49 blocks, all resident in wave 1 -> lookback cannot deadlock.
// ---------------------------------------------------------------------------
__global__ void scan_onepass_kernel(int n_nodes, int n_edges) {
    __shared__ int wsum[32];
    __shared__ int s_excl;
    const int tid = threadIdx.x;
    const int lane = tid & 31;
    const int warp = tid >> 5;
    const int bid = blockIdx.x;
    const int i = bid * SCAN_BLK + tid;

    int v = (i < n_nodes) ? g_deg[i] : 0;
    if (i < n_nodes) g_deg[i] = 0;   // restore for next replay

    int incl = v;
#pragma unroll
    for (int off = 1; off < 32; off <<= 1) {
        int t = __shfl_up_sync(0xFFFFFFFFu, incl, off);
        if (lane >= off) incl += t;
    }
    if (lane == 31) wsum[warp] = incl;
    __syncthreads();
    if (warp == 0) {
        int wv = wsum[lane];
        int winc = wv;
#pragma unroll
        for (int off = 1; off < 32; off <<= 1) {
            int t = __shfl_up_sync(0xFFFFFFFFu, winc, off);
            if (lane >= off) winc += t;
        }
        wsum[lane] = winc - wv;  // exclusive warp offsets
        int tot = __shfl_sync(0xFFFFFFFFu, winc, 31);
        if (lane == 0) {
            g_aggval[bid] = tot;
            __threadfence();
            atomicExch(&g_state[bid], 1);
            int excl = 0;
            for (int p = bid - 1; p >= 0;) {
                int st;
                do { st = atomicAdd(&g_state[p], 0); } while (st == 0);
                if (st == 2) { excl += atomicAdd(&g_prefval[p], 0); break; }
                excl += atomicAdd(&g_aggval[p], 0);
                p--;
            }
            g_prefval[bid] = excl + tot;
            __threadfence();
            atomicExch(&g_state[bid], 2);
            s_excl = excl;
        }
    }
    __syncthreads();

    if (i < n_nodes) {
        int r = incl - v + wsum[warp] + s_excl;
        g_rowptr[i] = r;
        g_cursor[i] = r;
    }
    if (i == 0) g_rowptr[n_nodes] = n_edges;
}

// ---------------------------------------------------------------------------
// scatter sources into CSR slots; re-zero lookback state for next replay
// ---------------------------------------------------------------------------
__global__ void scatter_kernel(const int2* __restrict__ edges, int n_edges) {
    int e = blockIdx.x * blockDim.x + threadIdx.x;
    if (e < MAX_SCAN_BLOCKS) g_state[e] = 0;
    if (e >= n_edges) return;
    int2 ed = edges[e];
    int pos = atomicAdd(&g_cursor[ed.y], 1);
    g_csrc[pos] = ed.x;
}

// ---------------------------------------------------------------------------
// fused attention: one warp per target node, MLP=4 pipelined main loop.
// out[tgt] = gelu( (sum_e p_e * xp[src_e]) / (sum_e p_e + 1e-7) + bias )
// leaky_relu(s) = max(s, 0.2*s) since slope < 1.
// ---------------------------------------------------------------------------
__device__ __forceinline__ float gelu_tanh(float v) {
    float c = 0.7978845608028654f * (v + 0.044715f * v * v * v);
    return 0.5f * v * (1.f + tanhf(c));
}

__global__ void attn_kernel(const float* __restrict__ ka1,
                            const float* __restrict__ battn,
                            const float* __restrict__ bias,
                            float* __restrict__ out,
                            int n_nodes) {
    int w = (blockIdx.x * blockDim.x + threadIdx.x) >> 5;
    if (w >= n_nodes) return;
    const int lane = threadIdx.x & 31;
    const int j = lane * 4;

    const int row = __ldg(&g_rowptr[w]);
    const int end = __ldg(&g_rowptr[w + 1]);

    const float4 xt = *reinterpret_cast<const float4*>(&g_xp[(size_t)w * D + j]);
    const float4 kb = *reinterpret_cast<const float4*>(&battn[j]);
    const float4 ka = *reinterpret_cast<const float4*>(&ka1[j]);

    const float tb0 = xt.x + 2.f * kb.x;
    const float tb1 = xt.y + 2.f * kb.y;
    const float tb2 = xt.z + 2.f * kb.z;
    const float tb3 = xt.w + 2.f * kb.w;

    float a0 = 0.f, a1 = 0.f, a2 = 0.f, a3 = 0.f, ssum = 0.f;

    auto process = [&](float4 xv) {
        float s0 = xv.x + tb0; s0 = fmaxf(s0, 0.2f * s0);
        float s1 = xv.y + tb1; s1 = fmaxf(s1, 0.2f * s1);
        float s2 = xv.z + tb2; s2 = fmaxf(s2, 0.2f * s2);
        float s3 = xv.w + tb3; s3 = fmaxf(s3, 0.2f * s3);
        float part = fmaf(s0, ka.x, fmaf(s1, ka.y, fmaf(s2, ka.z, s3 * ka.w)));
        part += __shfl_xor_sync(0xFFFFFFFFu, part, 1);
        part += __shfl_xor_sync(0xFFFFFFFFu, part, 2);
        float p = __expf(part);
        ssum += p;
        a0 = fmaf(p, xv.x, a0);
        a1 = fmaf(p, xv.y, a1);
        a2 = fmaf(p, xv.z, a2);
        a3 = fmaf(p, xv.w, a3);
    };

    int e = row;
    // pipelined main loop: batch 4 indices, issue 4 independent gathers
    for (; e + 4 <= end; e += 4) {
        int s0i = __ldg(&g_csrc[e + 0]);
        int s1i = __ldg(&g_csrc[e + 1]);
        int s2i = __ldg(&g_csrc[e + 2]);
        int s3i = __ldg(&g_csrc[e + 3]);
        float4 v0 = *reinterpret_cast<const float4*>(&g_xp[(size_t)s0i * D + j]);
        float4 v1 = *reinterpret_cast<const float4*>(&g_xp[(size_t)s1i * D + j]);
        float4 v2 = *reinterpret_cast<const float4*>(&g_xp[(size_t)s2i * D + j]);
        float4 v3 = *reinterpret_cast<const float4*>(&g_xp[(size_t)s3i * D + j]);
        process(v0);
        process(v1);
        process(v2);
        process(v3);
    }
    // tail
    for (; e < end; e++) {
        int si = __ldg(&g_csrc[e]);
        float4 v = *reinterpret_cast<const float4*>(&g_xp[(size_t)si * D + j]);
        process(v);
    }

    const float inv = 1.f / (ssum + 1e-7f);
    const float4 b = *reinterpret_cast<const float4*>(&bias[j]);
    float4 o;
    o.x = gelu_tanh(fmaf(a0, inv, b.x));
    o.y = gelu_tanh(fmaf(a1, inv, b.y));
    o.z = gelu_tanh(fmaf(a2, inv, b.z));
    o.w = gelu_tanh(fmaf(a3, inv, b.w));
    *reinterpret_cast<float4*>(&out[(size_t)w * D + j]) = o;
}

// ---------------------------------------------------------------------------
extern "C" void kernel_launch(void* const* d_in, const int* in_sizes, int n_in,
                              void* d_out, int out_size) {
    const float* x     = (const float*)d_in[0];
    const int*   edges = (const int*)d_in[1];
    const float* W     = (const float*)d_in[2]; // (D, H, U) row-major == D x 128
    const float* ka1   = (const float*)d_in[3];
    const float* battn = (const float*)d_in[4];
    const float* bias  = (const float*)d_in[5];
    float* out = (float*)d_out;

    const int n_nodes = in_sizes[0] / D;
    const int n_edges = in_sizes[1] / 2;
    const int nb = (n_nodes + SCAN_BLK - 1) / SCAN_BLK;

    // One-time host-side stream/event setup (first call is the non-captured
    // correctness run; capture calls reuse these). No device allocations.
    static cudaStream_t s_side = nullptr;
    static cudaEvent_t ev_fork = nullptr, ev_join = nullptr;
    if (s_side == nullptr) {
        cudaStreamCreateWithFlags(&s_side, cudaStreamNonBlocking);
        cudaEventCreateWithFlags(&ev_fork, cudaEventDisableTiming);
        cudaEventCreateWithFlags(&ev_join, cudaEventDisableTiming);
    }

    // Fork: gemm on side stream, CSR build on main stream (independent).
    cudaEventRecord(ev_fork, 0);
    cudaStreamWaitEvent(s_side, ev_fork, 0);
    gemm_kernel<<<(n_nodes + 31) / 32, 128, 0, s_side>>>(x, W, n_nodes);
    cudaEventRecord(ev_join, s_side);

    // Main stream: in-degree histogram -> scan -> scatter
    hist_kernel<<<(n_edges + 255) / 256, 256>>>((const int2*)edges, n_edges);
    scan_onepass_kernel<<<nb, SCAN_BLK>>>(n_nodes, n_edges);
    scatter_kernel<<<(n_edges + 255) / 256, 256>>>((const int2*)edges, n_edges);

    // Join: attn needs both g_xp (gemm) and CSR (scatter)
    cudaStreamWaitEvent(0, ev_join, 0);
    {
        int threads = 256;
        int blocks = (n_nodes * 32 + threads - 1) / threads;
        attn_kernel<<<blocks, threads>>>(ka1, battn, bias, out, n_nodes);
    }
}